// round 2
// baseline (speedup 1.0000x reference)
#include <cuda_runtime.h>
#include <cuda_bf16.h>

#define NNODES 8192
#define NEDGES 262144
#define NFEAT  128

// ---------------- device scratch (no allocation allowed) ----------------
__device__ __align__(16) float g_support[NNODES * NFEAT];     // x @ W  (4 MB)
__device__ __align__(16) float g_deg[NNODES];
__device__ __align__(16) float g_dinv[NNODES];
__device__ __align__(16) int   g_cnt[NNODES];                 // per-row edge counts
__device__ __align__(16) int   g_row_ptr[NNODES + 1];         // CSR offsets
__device__ __align__(16) int   g_fill[NNODES];                // scatter cursors
__device__ __align__(16) int   g_ecol[NEDGES];                // CSR cols
__device__ __align__(16) float g_eval[NEDGES];                // CSR edge weights

// ---------------- K1: init ----------------
__global__ void k_init() {
    int i = blockIdx.x * blockDim.x + threadIdx.x;
    if (i < NNODES) {
        g_deg[i] = 1.0f;   // self-loop
        g_cnt[i] = 0;
    }
}

// ---------------- K2: edge pass 1 (degree + row histogram) ----------------
__global__ void k_edge_count(const int* __restrict__ rows,
                             const float* __restrict__ ew) {
    int e = blockIdx.x * blockDim.x + threadIdx.x;
    if (e < NEDGES) {
        int r = rows[e];
        atomicAdd(&g_deg[r], ew[e]);
        atomicAdd(&g_cnt[r], 1);
    }
}

// ---------------- K3: dinv ----------------
__global__ void k_dinv() {
    int i = blockIdx.x * blockDim.x + threadIdx.x;
    if (i < NNODES) g_dinv[i] = rsqrtf(g_deg[i] + 1e-10f);
}

// ---------------- K4: single-block exclusive scan over 8192 counts ----------------
__global__ void k_scan() {
    __shared__ int s[1024];
    int t = threadIdx.x;                 // 1024 threads, 8 counts each
    int c[8];
    int base_idx = t * 8;
    int run = 0;
#pragma unroll
    for (int j = 0; j < 8; j++) { c[j] = run; run += g_cnt[base_idx + j]; }
    s[t] = run;
    __syncthreads();
    // Hillis-Steele inclusive scan over 1024 chunk totals
    for (int off = 1; off < 1024; off <<= 1) {
        int v = (t >= off) ? s[t - off] : 0;
        __syncthreads();
        s[t] += v;
        __syncthreads();
    }
    int chunk_base = s[t] - run;         // exclusive base for this chunk
#pragma unroll
    for (int j = 0; j < 8; j++) {
        int v = chunk_base + c[j];
        g_row_ptr[base_idx + j] = v;
        g_fill[base_idx + j]    = v;
    }
    if (t == 1023) g_row_ptr[NNODES] = s[1023];
}

// ---------------- K5: edge pass 2 (scatter into CSR) ----------------
__global__ void k_edge_scatter(const int* __restrict__ rows,
                               const int* __restrict__ cols,
                               const float* __restrict__ ew) {
    int e = blockIdx.x * blockDim.x + threadIdx.x;
    if (e < NEDGES) {
        int r = rows[e];
        int pos = atomicAdd(&g_fill[r], 1);
        g_ecol[pos] = cols[e];
        g_eval[pos] = ew[e];
    }
}

// ---------------- K6: support = x @ W  (8192x128x128 fp32) ----------------
// Block: 256 threads, tile 32 rows x 128 cols, K chunks of 32.
// Each thread: 4 rows x 4 cols accumulators.
__global__ void k_gemm(const float* __restrict__ x,
                       const float* __restrict__ w) {
    __shared__ __align__(16) float s_x[32][32];
    __shared__ __align__(16) float s_w[32][128];
    int tid = threadIdx.x;
    int row_base = blockIdx.x * 32;
    int c0 = (tid & 31) * 4;      // 0..124
    int r0 = (tid >> 5) * 4;      // 0..28

    float acc[4][4];
#pragma unroll
    for (int i = 0; i < 4; i++)
#pragma unroll
        for (int j = 0; j < 4; j++) acc[i][j] = 0.0f;

    for (int kk = 0; kk < 128; kk += 32) {
#pragma unroll
        for (int q = 0; q < 4; q++) {
            int e = tid + 256 * q;
            int r = e >> 5, kl = e & 31;
            s_x[r][kl] = x[(row_base + r) * 128 + kk + kl];
        }
#pragma unroll
        for (int q = 0; q < 4; q++) {
            int p = tid + 256 * q;
            int kr = p >> 5, c4 = (p & 31) * 4;
            *(float4*)&s_w[kr][c4] = *(const float4*)&w[(kk + kr) * 128 + c4];
        }
        __syncthreads();
#pragma unroll
        for (int k = 0; k < 32; k++) {
            float4 b = *(float4*)&s_w[k][c0];
            float a0 = s_x[r0 + 0][k];
            float a1 = s_x[r0 + 1][k];
            float a2 = s_x[r0 + 2][k];
            float a3 = s_x[r0 + 3][k];
            acc[0][0] += a0 * b.x; acc[0][1] += a0 * b.y; acc[0][2] += a0 * b.z; acc[0][3] += a0 * b.w;
            acc[1][0] += a1 * b.x; acc[1][1] += a1 * b.y; acc[1][2] += a1 * b.z; acc[1][3] += a1 * b.w;
            acc[2][0] += a2 * b.x; acc[2][1] += a2 * b.y; acc[2][2] += a2 * b.z; acc[2][3] += a2 * b.w;
            acc[3][0] += a3 * b.x; acc[3][1] += a3 * b.y; acc[3][2] += a3 * b.z; acc[3][3] += a3 * b.w;
        }
        __syncthreads();
    }
#pragma unroll
    for (int i = 0; i < 4; i++) {
        float4 v = make_float4(acc[i][0], acc[i][1], acc[i][2], acc[i][3]);
        *(float4*)&g_support[(row_base + r0 + i) * 128 + c0] = v;
    }
}

// ---------------- K7: SpMM gather + normalize + bias ----------------
// One warp per output row; each lane owns 4 features (float4).
__global__ void k_spmm(const float* __restrict__ bias,
                       float* __restrict__ out) {
    int warp = (blockIdx.x * blockDim.x + threadIdx.x) >> 5;
    int lane = threadIdx.x & 31;
    if (warp >= NNODES) return;
    int row = warp;
    int s = g_row_ptr[row];
    int e = g_row_ptr[row + 1];
    float di = g_dinv[row];

    float ax = 0.f, ay = 0.f, az = 0.f, aw = 0.f;
    int foff = lane * 4;

    int i = s;
    for (; i + 1 < e; i += 2) {
        int   c0 = g_ecol[i],     c1 = g_ecol[i + 1];
        float v0 = g_eval[i] * g_dinv[c0];
        float v1 = g_eval[i + 1] * g_dinv[c1];
        float4 s0 = *(const float4*)&g_support[c0 * 128 + foff];
        float4 s1 = *(const float4*)&g_support[c1 * 128 + foff];
        ax += v0 * s0.x + v1 * s1.x;
        ay += v0 * s0.y + v1 * s1.y;
        az += v0 * s0.z + v1 * s1.z;
        aw += v0 * s0.w + v1 * s1.w;
    }
    if (i < e) {
        int   c0 = g_ecol[i];
        float v0 = g_eval[i] * g_dinv[c0];
        float4 s0 = *(const float4*)&g_support[c0 * 128 + foff];
        ax += v0 * s0.x; ay += v0 * s0.y; az += v0 * s0.z; aw += v0 * s0.w;
    }
    // self-loop: dinv[row]^2 * support[row]
    {
        float4 sv = *(const float4*)&g_support[row * 128 + foff];
        ax += di * sv.x; ay += di * sv.y; az += di * sv.z; aw += di * sv.w;
    }
    float4 b = *(const float4*)&bias[foff];
    float4 o;
    o.x = di * ax + b.x;
    o.y = di * ay + b.y;
    o.z = di * az + b.z;
    o.w = di * aw + b.w;
    *(float4*)&out[row * 128 + foff] = o;
}

// ---------------- launch ----------------
extern "C" void kernel_launch(void* const* d_in, const int* in_sizes, int n_in,
                              void* d_out, int out_size) {
    const float* x    = (const float*)d_in[0];
    const int*   adj  = (const int*)d_in[1];     // int32 [2, E] (JAX x64 disabled)
    const float* ew   = (const float*)d_in[2];
    const float* wgt  = (const float*)d_in[3];
    const float* bias = (const float*)d_in[4];
    float* out = (float*)d_out;

    const int* rows = adj;
    const int* cols = adj + NEDGES;

    k_init<<<(NNODES + 255) / 256, 256>>>();
    k_edge_count<<<(NEDGES + 255) / 256, 256>>>(rows, ew);
    k_dinv<<<(NNODES + 255) / 256, 256>>>();
    k_scan<<<1, 1024>>>();
    k_edge_scatter<<<(NEDGES + 255) / 256, 256>>>(rows, cols, ew);
    k_gemm<<<NNODES / 32, 256>>>(x, wgt);
    k_spmm<<<NNODES / 8, 256>>>(bias, out);
}

// round 3
// speedup vs baseline: 1.5215x; 1.5215x over previous
#include <cuda_runtime.h>
#include <cuda_bf16.h>

#define NNODES 8192
#define NEDGES 262144
#define NFEAT  128

// ---------------- device scratch (no allocation allowed) ----------------
__device__ __align__(16) float g_support[NNODES * NFEAT];     // x @ W  (4 MB)
__device__ __align__(16) float g_deg[NNODES];
__device__ __align__(16) float g_dinv[NNODES];
__device__ __align__(16) int   g_cnt[NNODES];                 // per-row edge counts
__device__ __align__(16) int   g_row_ptr[NNODES + 1];         // CSR offsets
__device__ __align__(16) int   g_fill[NNODES];                // scatter cursors
__device__ __align__(16) int   g_ecol[NEDGES];                // CSR cols
__device__ __align__(16) float g_eval[NEDGES];                // CSR edge weights

// ---------------- K1: init ----------------
__global__ void k_init() {
    int i = blockIdx.x * blockDim.x + threadIdx.x;
    if (i < NNODES) {
        g_deg[i] = 1.0f;   // self-loop
        g_cnt[i] = 0;
    }
}

// ---------------- K2: edge pass 1 (degree + row histogram) ----------------
__global__ void k_edge_count(const int* __restrict__ rows,
                             const float* __restrict__ ew) {
    int e = blockIdx.x * blockDim.x + threadIdx.x;
    if (e < NEDGES) {
        int r = rows[e];
        atomicAdd(&g_deg[r], ew[e]);
        atomicAdd(&g_cnt[r], 1);
    }
}

// ---------------- K3: shfl scan over 8192 counts + fused dinv ----------------
// 1024 threads, 8 counts/thread, 2 barriers total.
__global__ __launch_bounds__(1024) void k_scan() {
    __shared__ int warp_tot[32];
    int t    = threadIdx.x;
    int lane = t & 31;
    int wid  = t >> 5;
    int base_idx = t * 8;

    int4 a = *(const int4*)&g_cnt[base_idx];
    int4 b = *(const int4*)&g_cnt[base_idx + 4];
    int c[8] = {a.x, a.y, a.z, a.w, b.x, b.y, b.z, b.w};
    int ex[8];
    int run = 0;
#pragma unroll
    for (int j = 0; j < 8; j++) { ex[j] = run; run += c[j]; }

    // inclusive warp scan of per-thread totals
    int v = run;
#pragma unroll
    for (int off = 1; off < 32; off <<= 1) {
        int u = __shfl_up_sync(0xffffffffu, v, off);
        if (lane >= off) v += u;
    }
    if (lane == 31) warp_tot[wid] = v;
    __syncthreads();
    if (wid == 0) {
        int w = warp_tot[lane];
#pragma unroll
        for (int off = 1; off < 32; off <<= 1) {
            int u = __shfl_up_sync(0xffffffffu, w, off);
            if (lane >= off) w += u;
        }
        warp_tot[lane] = w;   // inclusive warp totals
    }
    __syncthreads();

    int chunk_base = v - run + (wid ? warp_tot[wid - 1] : 0);
    int4 o0 = make_int4(chunk_base + ex[0], chunk_base + ex[1],
                        chunk_base + ex[2], chunk_base + ex[3]);
    int4 o1 = make_int4(chunk_base + ex[4], chunk_base + ex[5],
                        chunk_base + ex[6], chunk_base + ex[7]);
    *(int4*)&g_row_ptr[base_idx]     = o0;
    *(int4*)&g_row_ptr[base_idx + 4] = o1;
    *(int4*)&g_fill[base_idx]        = o0;
    *(int4*)&g_fill[base_idx + 4]    = o1;
    if (t == 1023) g_row_ptr[NNODES] = warp_tot[31];

    // fused dinv (deg is final after k_edge_count)
    float4 d0 = *(const float4*)&g_deg[base_idx];
    float4 d1 = *(const float4*)&g_deg[base_idx + 4];
    float4 r0 = make_float4(rsqrtf(d0.x + 1e-10f), rsqrtf(d0.y + 1e-10f),
                            rsqrtf(d0.z + 1e-10f), rsqrtf(d0.w + 1e-10f));
    float4 r1 = make_float4(rsqrtf(d1.x + 1e-10f), rsqrtf(d1.y + 1e-10f),
                            rsqrtf(d1.z + 1e-10f), rsqrtf(d1.w + 1e-10f));
    *(float4*)&g_dinv[base_idx]     = r0;
    *(float4*)&g_dinv[base_idx + 4] = r1;
}

// ---------------- K4: edge pass 2 (scatter into CSR) ----------------
__global__ void k_edge_scatter(const int* __restrict__ rows,
                               const int* __restrict__ cols,
                               const float* __restrict__ ew) {
    int e = blockIdx.x * blockDim.x + threadIdx.x;
    if (e < NEDGES) {
        int r = rows[e];
        int pos = atomicAdd(&g_fill[r], 1);
        g_ecol[pos] = cols[e];
        g_eval[pos] = ew[e];
    }
}

// ---------------- packed f32x2 helpers ----------------
__device__ __forceinline__ unsigned long long pack2(float lo, float hi) {
    unsigned long long r;
    asm("mov.b64 %0, {%1, %2};" : "=l"(r) : "f"(lo), "f"(hi));
    return r;
}
__device__ __forceinline__ void fma2(unsigned long long& d,
                                     unsigned long long a,
                                     unsigned long long b) {
    asm("fma.rn.f32x2 %0, %1, %2, %0;" : "+l"(d) : "l"(a), "l"(b));
}
__device__ __forceinline__ float2 unpack2(unsigned long long p) {
    float lo, hi;
    asm("mov.b64 {%0, %1}, %2;" : "=f"(lo), "=f"(hi) : "l"(p));
    return make_float2(lo, hi);
}

// ---------------- K5: support = x @ W  (8192x128x128 fp32, f32x2 FMA) -------
// Block: 256 threads, tile 32 rows x 128 cols, K chunks of 32.
__global__ __launch_bounds__(256) void k_gemm(const float* __restrict__ x,
                                              const float* __restrict__ w) {
    __shared__ __align__(16) float s_x[32][32];
    __shared__ __align__(16) float s_w[32][128];
    int tid = threadIdx.x;
    int row_base = blockIdx.x * 32;
    int c0 = (tid & 31) * 4;      // 0..124
    int r0 = (tid >> 5) * 4;      // 0..28

    unsigned long long acc2[4][2];
#pragma unroll
    for (int i = 0; i < 4; i++) { acc2[i][0] = 0ull; acc2[i][1] = 0ull; }

    for (int kk = 0; kk < 128; kk += 32) {
#pragma unroll
        for (int q = 0; q < 4; q++) {
            int e = tid + 256 * q;
            int r = e >> 5, kl = e & 31;
            s_x[r][kl] = x[(row_base + r) * 128 + kk + kl];
        }
#pragma unroll
        for (int q = 0; q < 4; q++) {
            int p = tid + 256 * q;
            int kr = p >> 5, c4 = (p & 31) * 4;
            *(float4*)&s_w[kr][c4] = *(const float4*)&w[(kk + kr) * 128 + c4];
        }
        __syncthreads();
#pragma unroll
        for (int k = 0; k < 32; k++) {
            float4 bv = *(float4*)&s_w[k][c0];
            unsigned long long b01 = pack2(bv.x, bv.y);
            unsigned long long b23 = pack2(bv.z, bv.w);
#pragma unroll
            for (int i = 0; i < 4; i++) {
                float av = s_x[r0 + i][k];
                unsigned long long aa = pack2(av, av);
                fma2(acc2[i][0], aa, b01);
                fma2(acc2[i][1], aa, b23);
            }
        }
        __syncthreads();
    }
#pragma unroll
    for (int i = 0; i < 4; i++) {
        float2 lo = unpack2(acc2[i][0]);
        float2 hi = unpack2(acc2[i][1]);
        float4 v = make_float4(lo.x, lo.y, hi.x, hi.y);
        *(float4*)&g_support[(row_base + r0 + i) * 128 + c0] = v;
    }
}

// ---------------- K6: SpMM gather + normalize + bias ----------------
// One warp per output row; each lane owns 4 features (float4). Unroll 4.
__global__ __launch_bounds__(256) void k_spmm(const float* __restrict__ bias,
                                              float* __restrict__ out) {
    int warp = (blockIdx.x * blockDim.x + threadIdx.x) >> 5;
    int lane = threadIdx.x & 31;
    if (warp >= NNODES) return;
    int row = warp;
    int s = g_row_ptr[row];
    int e = g_row_ptr[row + 1];
    float di = g_dinv[row];

    float ax = 0.f, ay = 0.f, az = 0.f, aw = 0.f;
    int foff = lane * 4;

    int i = s;
    for (; i + 3 < e; i += 4) {
        int c0 = g_ecol[i];
        int c1 = g_ecol[i + 1];
        int c2 = g_ecol[i + 2];
        int c3 = g_ecol[i + 3];
        float v0 = g_eval[i]     * g_dinv[c0];
        float v1 = g_eval[i + 1] * g_dinv[c1];
        float v2 = g_eval[i + 2] * g_dinv[c2];
        float v3 = g_eval[i + 3] * g_dinv[c3];
        float4 s0 = *(const float4*)&g_support[c0 * 128 + foff];
        float4 s1 = *(const float4*)&g_support[c1 * 128 + foff];
        float4 s2 = *(const float4*)&g_support[c2 * 128 + foff];
        float4 s3 = *(const float4*)&g_support[c3 * 128 + foff];
        ax += v0 * s0.x + v1 * s1.x + v2 * s2.x + v3 * s3.x;
        ay += v0 * s0.y + v1 * s1.y + v2 * s2.y + v3 * s3.y;
        az += v0 * s0.z + v1 * s1.z + v2 * s2.z + v3 * s3.z;
        aw += v0 * s0.w + v1 * s1.w + v2 * s2.w + v3 * s3.w;
    }
    for (; i < e; i++) {
        int   c0 = g_ecol[i];
        float v0 = g_eval[i] * g_dinv[c0];
        float4 s0 = *(const float4*)&g_support[c0 * 128 + foff];
        ax += v0 * s0.x; ay += v0 * s0.y; az += v0 * s0.z; aw += v0 * s0.w;
    }
    // self-loop: dinv[row]^2 * support[row]
    {
        float4 sv = *(const float4*)&g_support[row * 128 + foff];
        ax += di * sv.x; ay += di * sv.y; az += di * sv.z; aw += di * sv.w;
    }
    float4 b = *(const float4*)&bias[foff];
    float4 o;
    o.x = di * ax + b.x;
    o.y = di * ay + b.y;
    o.z = di * az + b.z;
    o.w = di * aw + b.w;
    *(float4*)&out[row * 128 + foff] = o;
}

// ---------------- launch ----------------
extern "C" void kernel_launch(void* const* d_in, const int* in_sizes, int n_in,
                              void* d_out, int out_size) {
    const float* x    = (const float*)d_in[0];
    const int*   adj  = (const int*)d_in[1];     // int32 [2, E]
    const float* ew   = (const float*)d_in[2];
    const float* wgt  = (const float*)d_in[3];
    const float* bias = (const float*)d_in[4];
    float* out = (float*)d_out;

    const int* rows = adj;
    const int* cols = adj + NEDGES;

    k_init<<<(NNODES + 255) / 256, 256>>>();
    k_edge_count<<<(NEDGES + 255) / 256, 256>>>(rows, ew);
    k_scan<<<1, 1024>>>();
    k_edge_scatter<<<(NEDGES + 255) / 256, 256>>>(rows, cols, ew);
    k_gemm<<<NNODES / 32, 256>>>(x, wgt);
    k_spmm<<<NNODES / 8, 256>>>(bias, out);
}